// round 10
// baseline (speedup 1.0000x reference)
#include <cuda_runtime.h>

#define B_  4
#define N_  1024
#define D_  512
#define H_  8
#define E_  5
#define HD_ 64

// ---- scratch (static device globals: no allocation in kernel_launch) ----
__device__ float g_q[B_*H_*N_*HD_];            // 8 MB  (b,h,n,hd)
__device__ float g_k[B_*H_*N_*HD_];            // 8 MB
__device__ float g_v[B_*H_*N_*HD_];            // 8 MB
__device__ float g_s[(size_t)B_*H_*N_*N_];     // 128 MB (b,h,n,m) scores/attn
__device__ float g_att[B_*N_*D_];              // 8 MB  (b,n,d) pre-proj

// ============================================================
// K1: qkv = x @ w_qkv^T   (4096 x 1536 x 512), scatter into q/k/v (b,h,n,hd)
// ============================================================
__global__ __launch_bounds__(256) void qkv_gemm(const float* __restrict__ x,
                                                const float* __restrict__ w) {
    __shared__ float As[8][128];
    __shared__ float Bs[8][128];
    const int tid = threadIdx.x;
    const int m0 = blockIdx.y * 128;
    const int c0 = blockIdx.x * 128;
    const int tx = tid & 15, ty = tid >> 4;
    float acc[8][8];
#pragma unroll
    for (int i = 0; i < 8; i++)
#pragma unroll
        for (int j = 0; j < 8; j++) acc[i][j] = 0.f;

    const int lrow = tid >> 1;
    const int lc   = (tid & 1) * 4;
    const float* ap = x + (size_t)(m0 + lrow) * D_ + lc;
    const float* bp = w + (size_t)(c0 + lrow) * D_ + lc;

    for (int k0 = 0; k0 < D_; k0 += 8) {
        float4 av = *(const float4*)(ap + k0);
        float4 bv = *(const float4*)(bp + k0);
        As[lc+0][lrow] = av.x; As[lc+1][lrow] = av.y;
        As[lc+2][lrow] = av.z; As[lc+3][lrow] = av.w;
        Bs[lc+0][lrow] = bv.x; Bs[lc+1][lrow] = bv.y;
        Bs[lc+2][lrow] = bv.z; Bs[lc+3][lrow] = bv.w;
        __syncthreads();
#pragma unroll
        for (int k = 0; k < 8; k++) {
            float4 a0 = *(const float4*)&As[k][ty*8];
            float4 a1 = *(const float4*)&As[k][ty*8+4];
            float4 b0 = *(const float4*)&Bs[k][tx*8];
            float4 b1 = *(const float4*)&Bs[k][tx*8+4];
            float a[8] = {a0.x,a0.y,a0.z,a0.w,a1.x,a1.y,a1.z,a1.w};
            float b[8] = {b0.x,b0.y,b0.z,b0.w,b1.x,b1.y,b1.z,b1.w};
#pragma unroll
            for (int i = 0; i < 8; i++)
#pragma unroll
                for (int j = 0; j < 8; j++) acc[i][j] += a[i]*b[j];
        }
        __syncthreads();
    }
#pragma unroll
    for (int j = 0; j < 8; j++) {
        int c  = c0 + tx*8 + j;
        int part = c >> 9;          // 0=q 1=k 2=v
        int h    = (c >> 6) & 7;
        int hd   = c & 63;
        float* dst = (part == 0) ? g_q : (part == 1) ? g_k : g_v;
#pragma unroll
        for (int i = 0; i < 8; i++) {
            int m  = m0 + ty*8 + i;
            int bb = m >> 10, n = m & 1023;
            dst[(((bb*H_ + h)*N_ + n) << 6) + hd] = acc[i][j];
        }
    }
}

// ============================================================
// K2: g_s = scale * q @ k^T   per (b,h). 128x128 tile, K=64, BK=8. Pure store.
// ============================================================
__global__ __launch_bounds__(256) void qk_gemm() {
    __shared__ float As[8][128];
    __shared__ float Bs[8][128];
    const int tid = threadIdx.x;
    const int z  = blockIdx.z;
    const int n0 = blockIdx.y * 128;   // query rows
    const int m0 = blockIdx.x * 128;   // key cols
    const float* A  = g_q + (size_t)z * N_ * HD_;
    const float* Bm = g_k + (size_t)z * N_ * HD_;
    float*       C  = g_s + (size_t)z * N_ * N_;
    const int tx = tid & 15, ty = tid >> 4;
    float acc[8][8];
#pragma unroll
    for (int i = 0; i < 8; i++)
#pragma unroll
        for (int j = 0; j < 8; j++) acc[i][j] = 0.f;

    const int lrow = tid >> 1;
    const int lc   = (tid & 1) * 4;
    const float* ap = A  + (size_t)(n0 + lrow) * HD_ + lc;
    const float* bp = Bm + (size_t)(m0 + lrow) * HD_ + lc;

    for (int k0 = 0; k0 < HD_; k0 += 8) {
        float4 av = *(const float4*)(ap + k0);
        float4 bv = *(const float4*)(bp + k0);
        As[lc+0][lrow] = av.x; As[lc+1][lrow] = av.y;
        As[lc+2][lrow] = av.z; As[lc+3][lrow] = av.w;
        Bs[lc+0][lrow] = bv.x; Bs[lc+1][lrow] = bv.y;
        Bs[lc+2][lrow] = bv.z; Bs[lc+3][lrow] = bv.w;
        __syncthreads();
#pragma unroll
        for (int k = 0; k < 8; k++) {
            float4 a0 = *(const float4*)&As[k][ty*8];
            float4 a1 = *(const float4*)&As[k][ty*8+4];
            float4 b0 = *(const float4*)&Bs[k][tx*8];
            float4 b1 = *(const float4*)&Bs[k][tx*8+4];
            float a[8] = {a0.x,a0.y,a0.z,a0.w,a1.x,a1.y,a1.z,a1.w};
            float b[8] = {b0.x,b0.y,b0.z,b0.w,b1.x,b1.y,b1.z,b1.w};
#pragma unroll
            for (int i = 0; i < 8; i++)
#pragma unroll
                for (int j = 0; j < 8; j++) acc[i][j] += a[i]*b[j];
        }
        __syncthreads();
    }
    const float scale = 0.125f;   // 64^-0.5
#pragma unroll
    for (int i = 0; i < 8; i++) {
        int row = n0 + ty*8 + i;
        float4* p = (float4*)(C + (size_t)row * N_ + m0 + tx*8);
        p[0] = make_float4(scale*acc[i][0], scale*acc[i][1],
                           scale*acc[i][2], scale*acc[i][3]);
        p[1] = make_float4(scale*acc[i][4], scale*acc[i][5],
                           scale*acc[i][6], scale*acc[i][7]);
    }
}

// ============================================================
// K3: fused edge-bias + masked softmax. One block per (b,n), covers all H heads.
//   eb[h][m] = sigmoid(e.w_eg[h]+b_eg[h]) * (e.w_ep[h])   (edge read once)
//   attn[h][n][:] = softmax(scores + eb) with pair mask; invalid rows -> 1/N.
// mask arrives as int32 (bool upcast by harness).
// ============================================================
__global__ __launch_bounds__(256) void bias_softmax(const float* __restrict__ edge,
                                                    const int* __restrict__ mask,
                                                    const float* __restrict__ w_ep,
                                                    const float* __restrict__ w_eg,
                                                    const float* __restrict__ b_eg) {
    __shared__ float eb[H_][N_];          // 32 KB
    __shared__ unsigned char mk[N_];      // 1 KB
    __shared__ float swp[H_*E_], swg[H_*E_], sbg[H_];
    __shared__ float red_max[8], red_sum[8];

    const int tid = threadIdx.x;
    const int bn  = blockIdx.x;           // b*N + n
    const int b   = bn >> 10, n = bn & 1023;

    if (tid < H_*E_)                 swp[tid]           = w_ep[tid];
    else if (tid < 2*H_*E_)          swg[tid - H_*E_]   = w_eg[tid - H_*E_];
    else if (tid < 2*H_*E_ + H_)     sbg[tid - 2*H_*E_] = b_eg[tid - 2*H_*E_];

    for (int m = tid; m < N_; m += 256)
        mk[m] = (mask[b*N_ + m] != 0) ? 1 : 0;
    __syncthreads();

    // precompute gate*bias for all heads; edge row read once from GMEM
    const float* erow = edge + (size_t)bn * (N_*E_);
    int any = 0;
    for (int m = tid; m < N_; m += 256) {
        const float* e = erow + m*E_;
        float e0 = e[0], e1 = e[1], e2 = e[2], e3 = e[3], e4 = e[4];
#pragma unroll
        for (int h = 0; h < H_; h++) {
            float bias = e0*swp[h*5+0] + e1*swp[h*5+1] + e2*swp[h*5+2]
                       + e3*swp[h*5+3] + e4*swp[h*5+4];
            float gx   = e0*swg[h*5+0] + e1*swg[h*5+1] + e2*swg[h*5+2]
                       + e3*swg[h*5+3] + e4*swg[h*5+4] + sbg[h];
            eb[h][m] = bias / (1.0f + __expf(-gx));
        }
        any |= mk[m];
    }
    any = __syncthreads_or(any);          // barrier: eb + mk ready, row-any reduced

    const int rowvalid = (mk[n] != 0) && any;
    if (!rowvalid) {
        const float u = 1.0f / (float)N_;
#pragma unroll
        for (int h = 0; h < H_; h++) {
            float* srow = g_s + ((size_t)((b*H_ + h)*N_) + n) * N_;
#pragma unroll
            for (int kk = 0; kk < 4; kk++) srow[tid + kk*256] = u;
        }
        return;
    }

    const int wid = tid >> 5, lane = tid & 31;
#pragma unroll
    for (int h = 0; h < H_; h++) {
        float* srow = g_s + ((size_t)((b*H_ + h)*N_) + n) * N_;
        float v[4]; int vm[4];
        float mx = -3.402823466e38f;
#pragma unroll
        for (int kk = 0; kk < 4; kk++) {
            int m = tid + kk*256;
            vm[kk] = mk[m];
            float s = srow[m] + eb[h][m];
            v[kk] = s;
            if (vm[kk]) mx = fmaxf(mx, s);
        }
#pragma unroll
        for (int o = 16; o; o >>= 1) mx = fmaxf(mx, __shfl_xor_sync(0xffffffffu, mx, o));
        if (lane == 0) red_max[wid] = mx;
        __syncthreads();
        float mxa = red_max[0];
#pragma unroll
        for (int i = 1; i < 8; i++) mxa = fmaxf(mxa, red_max[i]);

        float sum = 0.f;
#pragma unroll
        for (int kk = 0; kk < 4; kk++) {
            float e = vm[kk] ? __expf(v[kk] - mxa) : 0.f;
            v[kk] = e; sum += e;
        }
#pragma unroll
        for (int o = 16; o; o >>= 1) sum += __shfl_xor_sync(0xffffffffu, sum, o);
        if (lane == 0) red_sum[wid] = sum;
        __syncthreads();
        float tot = 0.f;
#pragma unroll
        for (int i = 0; i < 8; i++) tot += red_sum[i];
        float inv = 1.0f / tot;
#pragma unroll
        for (int kk = 0; kk < 4; kk++) srow[tid + kk*256] = v[kk]*inv;
        __syncthreads();                  // protect red_* for next head
    }
}

// ============================================================
// K4: g_att[b,n,h*64+d] = attn @ v   per (b,h). 128x64 tile, BK=16
// ============================================================
__global__ __launch_bounds__(256) void av_gemm() {
    __shared__ float As[16][128];
    __shared__ float Bs[16][64];
    const int tid = threadIdx.x;
    const int z  = blockIdx.y;
    const int n0 = blockIdx.x * 128;
    const float* A = g_s + (size_t)z * N_ * N_;
    const float* V = g_v + (size_t)z * N_ * HD_;
    const int tx = tid & 15, ty = tid >> 4;   // cols 16*4=64, rows 16*8=128
    float acc[8][4];
#pragma unroll
    for (int i = 0; i < 8; i++)
#pragma unroll
        for (int j = 0; j < 4; j++) acc[i][j] = 0.f;

    for (int k0 = 0; k0 < N_; k0 += 16) {
#pragma unroll
        for (int rr = 0; rr < 2; rr++) {
            int q    = tid*2 + rr;
            int arow = q >> 2;
            int ac   = (q & 3) * 4;
            float4 av = *(const float4*)(A + (size_t)(n0 + arow)*N_ + k0 + ac);
            As[ac+0][arow] = av.x; As[ac+1][arow] = av.y;
            As[ac+2][arow] = av.z; As[ac+3][arow] = av.w;
        }
        {
            int krow = tid >> 4;
            int c4   = (tid & 15) * 4;
            *(float4*)&Bs[krow][c4] = *(const float4*)(V + (size_t)(k0 + krow)*HD_ + c4);
        }
        __syncthreads();
#pragma unroll
        for (int k = 0; k < 16; k++) {
            float4 a0 = *(const float4*)&As[k][ty*8];
            float4 a1 = *(const float4*)&As[k][ty*8+4];
            float4 bb = *(const float4*)&Bs[k][tx*4];
            float a[8] = {a0.x,a0.y,a0.z,a0.w,a1.x,a1.y,a1.z,a1.w};
            float b[4] = {bb.x,bb.y,bb.z,bb.w};
#pragma unroll
            for (int i = 0; i < 8; i++)
#pragma unroll
                for (int j = 0; j < 4; j++) acc[i][j] += a[i]*b[j];
        }
        __syncthreads();
    }
    const int b = z >> 3, h = z & 7;
#pragma unroll
    for (int i = 0; i < 8; i++) {
        int n = n0 + ty*8 + i;
        float4 o = make_float4(acc[i][0], acc[i][1], acc[i][2], acc[i][3]);
        *(float4*)&g_att[(size_t)(b*N_ + n)*D_ + h*HD_ + tx*4] = o;
    }
}

// ============================================================
// K5: out = g_att @ w_proj^T + b_proj   (4096 x 512 x 512)
// ============================================================
__global__ __launch_bounds__(256) void proj_gemm(const float* __restrict__ w,
                                                 const float* __restrict__ bias,
                                                 float* __restrict__ out) {
    __shared__ float As[8][128];
    __shared__ float Bs[8][128];
    const int tid = threadIdx.x;
    const int m0 = blockIdx.y * 128;
    const int c0 = blockIdx.x * 128;
    const int tx = tid & 15, ty = tid >> 4;
    float acc[8][8];
#pragma unroll
    for (int i = 0; i < 8; i++)
#pragma unroll
        for (int j = 0; j < 8; j++) acc[i][j] = 0.f;

    const int lrow = tid >> 1;
    const int lc   = (tid & 1) * 4;
    const float* ap = g_att + (size_t)(m0 + lrow) * D_ + lc;
    const float* bp = w     + (size_t)(c0 + lrow) * D_ + lc;

    for (int k0 = 0; k0 < D_; k0 += 8) {
        float4 av = *(const float4*)(ap + k0);
        float4 bv = *(const float4*)(bp + k0);
        As[lc+0][lrow] = av.x; As[lc+1][lrow] = av.y;
        As[lc+2][lrow] = av.z; As[lc+3][lrow] = av.w;
        Bs[lc+0][lrow] = bv.x; Bs[lc+1][lrow] = bv.y;
        Bs[lc+2][lrow] = bv.z; Bs[lc+3][lrow] = bv.w;
        __syncthreads();
#pragma unroll
        for (int k = 0; k < 8; k++) {
            float4 a0 = *(const float4*)&As[k][ty*8];
            float4 a1 = *(const float4*)&As[k][ty*8+4];
            float4 b0 = *(const float4*)&Bs[k][tx*8];
            float4 b1 = *(const float4*)&Bs[k][tx*8+4];
            float a[8] = {a0.x,a0.y,a0.z,a0.w,a1.x,a1.y,a1.z,a1.w};
            float b[8] = {b0.x,b0.y,b0.z,b0.w,b1.x,b1.y,b1.z,b1.w};
#pragma unroll
            for (int i = 0; i < 8; i++)
#pragma unroll
                for (int j = 0; j < 8; j++) acc[i][j] += a[i]*b[j];
        }
        __syncthreads();
    }
    float4 bi0 = *(const float4*)&bias[c0 + tx*8];
    float4 bi1 = *(const float4*)&bias[c0 + tx*8 + 4];
#pragma unroll
    for (int i = 0; i < 8; i++) {
        int m = m0 + ty*8 + i;
        float4 o0 = make_float4(acc[i][0]+bi0.x, acc[i][1]+bi0.y,
                                acc[i][2]+bi0.z, acc[i][3]+bi0.w);
        float4 o1 = make_float4(acc[i][4]+bi1.x, acc[i][5]+bi1.y,
                                acc[i][6]+bi1.z, acc[i][7]+bi1.w);
        float4* p = (float4*)(out + (size_t)m * D_ + c0 + tx*8);
        p[0] = o0; p[1] = o1;
    }
}

// ============================================================
extern "C" void kernel_launch(void* const* d_in, const int* in_sizes, int n_in,
                              void* d_out, int out_size) {
    const float* x      = (const float*)d_in[0];
    const float* edge   = (const float*)d_in[1];
    const int*   mask   = (const int*)d_in[2];     // bool -> int32 in harness
    const float* w_qkv  = (const float*)d_in[3];
    const float* w_ep   = (const float*)d_in[4];
    const float* w_eg   = (const float*)d_in[5];
    const float* b_eg   = (const float*)d_in[6];
    const float* w_proj = (const float*)d_in[7];
    const float* b_proj = (const float*)d_in[8];
    float* out = (float*)d_out;

    qkv_gemm    <<<dim3(3*D_/128, B_*N_/128), 256>>>(x, w_qkv);           // 12 x 32
    qk_gemm     <<<dim3(N_/128, N_/128, B_*H_), 256>>>();                 // 8 x 8 x 32
    bias_softmax<<<B_*N_, 256>>>(edge, mask, w_ep, w_eg, b_eg);           // 4096
    av_gemm     <<<dim3(N_/128, B_*H_), 256>>>();                         // 8 x 32
    proj_gemm   <<<dim3(D_/128, B_*N_/128), 256>>>(w_proj, b_proj, out);  // 4 x 32
}

// round 13
// speedup vs baseline: 1.0994x; 1.0994x over previous
#include <cuda_runtime.h>
#include <cuda_bf16.h>
#include <cstdint>

#define B_  4
#define N_  1024
#define D_  512
#define H_  8
#define E_  5
#define HD_ 64

// ---- scratch (static device globals) ----
__device__ float g_q[B_*H_*N_*HD_];            // (b,h,n,hd)
__device__ float g_k[B_*H_*N_*HD_];            // (b,h,n,hd)
__device__ float g_v[B_*H_*HD_*N_];            // (b,h,hd,n)  TRANSPOSED
__device__ float g_s[(size_t)B_*H_*N_*N_];     // (b,h,n,m) scores/attn
__device__ float g_att[B_*N_*D_];              // (b,n,d)

// ============================================================
// helpers
// ============================================================
__device__ __forceinline__ uint32_t smem_u32(const void* p) {
    uint32_t a;
    asm("{ .reg .u64 t; cvta.to.shared.u64 t, %1; cvt.u32.u64 %0, t; }"
        : "=r"(a) : "l"(p));
    return a;
}
#define SWZ(off) ((off) ^ (((off) >> 3) & 0x70))

__device__ __forceinline__ void ldm_x4(uint32_t addr, uint32_t& r0, uint32_t& r1,
                                       uint32_t& r2, uint32_t& r3) {
    asm volatile("ldmatrix.sync.aligned.m8n8.x4.shared.b16 {%0,%1,%2,%3}, [%4];"
                 : "=r"(r0), "=r"(r1), "=r"(r2), "=r"(r3) : "r"(addr));
}
__device__ __forceinline__ void mma_bf16(float* c, const uint32_t* a, const uint32_t* b) {
    asm volatile("mma.sync.aligned.m16n8k16.row.col.f32.bf16.bf16.f32 "
                 "{%0,%1,%2,%3}, {%4,%5,%6,%7}, {%8,%9}, {%0,%1,%2,%3};"
                 : "+f"(c[0]), "+f"(c[1]), "+f"(c[2]), "+f"(c[3])
                 : "r"(a[0]), "r"(a[1]), "r"(a[2]), "r"(a[3]), "r"(b[0]), "r"(b[1]));
}

// convert 32 fp32 -> hi/lo bf16, store swizzled into 128B-row smem tiles
__device__ __forceinline__ void cvt32(const float* __restrict__ src,
                                      char* hi, char* lo, int byte_base) {
#pragma unroll
    for (int p = 0; p < 8; p++) {
        float4 x = *(const float4*)(src + p*4);
        __nv_bfloat162 h01 = __floats2bfloat162_rn(x.x, x.y);
        __nv_bfloat162 h23 = __floats2bfloat162_rn(x.z, x.w);
        float l0 = x.x - __bfloat162float(h01.x);
        float l1 = x.y - __bfloat162float(h01.y);
        float l2 = x.z - __bfloat162float(h23.x);
        float l3 = x.w - __bfloat162float(h23.y);
        __nv_bfloat162 g01 = __floats2bfloat162_rn(l0, l1);
        __nv_bfloat162 g23 = __floats2bfloat162_rn(l2, l3);
        int o0 = SWZ(byte_base + p*8);
        int o1 = SWZ(byte_base + p*8 + 4);
        *(uint32_t*)(hi + o0) = *(uint32_t*)&h01;
        *(uint32_t*)(hi + o1) = *(uint32_t*)&h23;
        *(uint32_t*)(lo + o0) = *(uint32_t*)&g01;
        *(uint32_t*)(lo + o1) = *(uint32_t*)&g23;
    }
}

// ============================================================
// K1: qkv = x @ w_qkv^T, scatter q,k (b,h,n,hd); v TRANSPOSED (b,h,hd,n)
// ============================================================
__global__ __launch_bounds__(256) void qkv_gemm(const float* __restrict__ x,
                                                const float* __restrict__ w) {
    __shared__ float As[8][128];
    __shared__ float Bs[8][128];
    const int tid = threadIdx.x;
    const int m0 = blockIdx.y * 128;
    const int c0 = blockIdx.x * 128;
    const int tx = tid & 15, ty = tid >> 4;
    float acc[8][8];
#pragma unroll
    for (int i = 0; i < 8; i++)
#pragma unroll
        for (int j = 0; j < 8; j++) acc[i][j] = 0.f;

    const int lrow = tid >> 1;
    const int lc   = (tid & 1) * 4;
    const float* ap = x + (size_t)(m0 + lrow) * D_ + lc;
    const float* bp = w + (size_t)(c0 + lrow) * D_ + lc;

    for (int k0 = 0; k0 < D_; k0 += 8) {
        float4 av = *(const float4*)(ap + k0);
        float4 bv = *(const float4*)(bp + k0);
        As[lc+0][lrow] = av.x; As[lc+1][lrow] = av.y;
        As[lc+2][lrow] = av.z; As[lc+3][lrow] = av.w;
        Bs[lc+0][lrow] = bv.x; Bs[lc+1][lrow] = bv.y;
        Bs[lc+2][lrow] = bv.z; Bs[lc+3][lrow] = bv.w;
        __syncthreads();
#pragma unroll
        for (int k = 0; k < 8; k++) {
            float4 a0 = *(const float4*)&As[k][ty*8];
            float4 a1 = *(const float4*)&As[k][ty*8+4];
            float4 b0 = *(const float4*)&Bs[k][tx*8];
            float4 b1 = *(const float4*)&Bs[k][tx*8+4];
            float a[8] = {a0.x,a0.y,a0.z,a0.w,a1.x,a1.y,a1.z,a1.w};
            float b[8] = {b0.x,b0.y,b0.z,b0.w,b1.x,b1.y,b1.z,b1.w};
#pragma unroll
            for (int i = 0; i < 8; i++)
#pragma unroll
                for (int j = 0; j < 8; j++) acc[i][j] += a[i]*b[j];
        }
        __syncthreads();
    }
#pragma unroll
    for (int j = 0; j < 8; j++) {
        int c  = c0 + tx*8 + j;
        int part = c >> 9;          // 0=q 1=k 2=v
        int h    = (c >> 6) & 7;
        int hd   = c & 63;
#pragma unroll
        for (int i = 0; i < 8; i++) {
            int m  = m0 + ty*8 + i;
            int bb = m >> 10, n = m & 1023;
            if (part == 0)      g_q[(((bb*H_ + h)*N_ + n) << 6) + hd] = acc[i][j];
            else if (part == 1) g_k[(((bb*H_ + h)*N_ + n) << 6) + hd] = acc[i][j];
            else                g_v[(((bb*H_ + h)*HD_ + hd) << 10) + n] = acc[i][j];
        }
    }
}

// ============================================================
// K2: g_s = 0.125 * q @ k^T  per (b,h). mma.sync bf16 hi/lo split (3 passes).
// Block tile 128x128, K=64. 8 warps = 4(m) x 2(n); warp tile 32x64.
// ============================================================
#define QK_AH 0
#define QK_AL 16384
#define QK_BH 32768
#define QK_BL 49152
#define QK_SMEM 65536

__global__ void __launch_bounds__(256) qk_mma() {
    extern __shared__ char sm[];
    const uint32_t sb = smem_u32(sm);
    const int tid = threadIdx.x, lane = tid & 31, wid = tid >> 5;
    const int z = blockIdx.z, n0 = blockIdx.y * 128, m0 = blockIdx.x * 128;

    // load + hi/lo convert (rows of 64 fp32 = 128B bf16 rows)
    const int row = tid >> 1, hc = (tid & 1) * 32;
    cvt32(g_q + ((size_t)z*N_ + n0 + row)*HD_ + hc, sm+QK_AH, sm+QK_AL, row*128 + hc*2);
    cvt32(g_k + ((size_t)z*N_ + m0 + row)*HD_ + hc, sm+QK_BH, sm+QK_BL, row*128 + hc*2);
    __syncthreads();

    const int warp_m = (wid & 3) * 32, warp_n = (wid >> 2) * 64;
    float c[2][8][4];
#pragma unroll
    for (int i = 0; i < 2; i++)
#pragma unroll
        for (int j = 0; j < 8; j++)
#pragma unroll
            for (int q = 0; q < 4; q++) c[i][j][q] = 0.f;

    // ldmatrix lane addressing: mat = lane>>3; rows, then k+8 halves
    const int lr = (lane & 7) + ((lane >> 3) & 1) * 8;
    const int lk = (lane >> 4) * 16;

#pragma unroll
    for (int k0 = 0; k0 < 64; k0 += 16) {
        const int kb = k0*2 + lk;
        uint32_t ah[2][4], al[2][4], bh[8][2], bl[8][2];
#pragma unroll
        for (int mf = 0; mf < 2; mf++) {
            const int r = warp_m + mf*16 + lr;
            ldm_x4(sb + QK_AH + SWZ(r*128 + kb), ah[mf][0], ah[mf][1], ah[mf][2], ah[mf][3]);
            ldm_x4(sb + QK_AL + SWZ(r*128 + kb), al[mf][0], al[mf][1], al[mf][2], al[mf][3]);
        }
#pragma unroll
        for (int nb = 0; nb < 4; nb++) {
            const int r = warp_n + nb*16 + lr;
            uint32_t r0, r1, r2, r3;
            ldm_x4(sb + QK_BH + SWZ(r*128 + kb), r0, r1, r2, r3);
            bh[nb*2][0] = r0; bh[nb*2][1] = r2; bh[nb*2+1][0] = r1; bh[nb*2+1][1] = r3;
            ldm_x4(sb + QK_BL + SWZ(r*128 + kb), r0, r1, r2, r3);
            bl[nb*2][0] = r0; bl[nb*2][1] = r2; bl[nb*2+1][0] = r1; bl[nb*2+1][1] = r3;
        }
#pragma unroll
        for (int mf = 0; mf < 2; mf++)
#pragma unroll
            for (int nf = 0; nf < 8; nf++) {
                mma_bf16(c[mf][nf], ah[mf], bh[nf]);
                mma_bf16(c[mf][nf], ah[mf], bl[nf]);
                mma_bf16(c[mf][nf], al[mf], bh[nf]);
            }
    }

    // epilogue: frag (m16n8): c0,c1 row=lane/4 col=(lane%4)*2; c2,c3 row+8
    const float sc = 0.125f;
    const int er = lane >> 2, ec = (lane & 3) * 2;
    float* C = g_s + (size_t)z*N_*N_;
#pragma unroll
    for (int mf = 0; mf < 2; mf++)
#pragma unroll
        for (int nf = 0; nf < 8; nf++) {
            const int rr = n0 + warp_m + mf*16 + er;
            const int cc = m0 + warp_n + nf*8 + ec;
            *(float2*)&C[(size_t)rr*N_ + cc] =
                make_float2(sc*c[mf][nf][0], sc*c[mf][nf][1]);
            *(float2*)&C[(size_t)(rr+8)*N_ + cc] =
                make_float2(sc*c[mf][nf][2], sc*c[mf][nf][3]);
        }
}

// ============================================================
// K3: fused edge-bias + masked softmax (unchanged, known good)
// ============================================================
__global__ __launch_bounds__(256) void bias_softmax(const float* __restrict__ edge,
                                                    const int* __restrict__ mask,
                                                    const float* __restrict__ w_ep,
                                                    const float* __restrict__ w_eg,
                                                    const float* __restrict__ b_eg) {
    __shared__ float eb[H_][N_];
    __shared__ unsigned char mk[N_];
    __shared__ float swp[H_*E_], swg[H_*E_], sbg[H_];
    __shared__ float red_max[8], red_sum[8];

    const int tid = threadIdx.x;
    const int bn  = blockIdx.x;
    const int b   = bn >> 10, n = bn & 1023;

    if (tid < H_*E_)                 swp[tid]           = w_ep[tid];
    else if (tid < 2*H_*E_)          swg[tid - H_*E_]   = w_eg[tid - H_*E_];
    else if (tid < 2*H_*E_ + H_)     sbg[tid - 2*H_*E_] = b_eg[tid - 2*H_*E_];

    for (int m = tid; m < N_; m += 256)
        mk[m] = (mask[b*N_ + m] != 0) ? 1 : 0;
    __syncthreads();

    const float* erow = edge + (size_t)bn * (N_*E_);
    int any = 0;
    for (int m = tid; m < N_; m += 256) {
        const float* e = erow + m*E_;
        float e0 = e[0], e1 = e[1], e2 = e[2], e3 = e[3], e4 = e[4];
#pragma unroll
        for (int h = 0; h < H_; h++) {
            float bias = e0*swp[h*5+0] + e1*swp[h*5+1] + e2*swp[h*5+2]
                       + e3*swp[h*5+3] + e4*swp[h*5+4];
            float gx   = e0*swg[h*5+0] + e1*swg[h*5+1] + e2*swg[h*5+2]
                       + e3*swg[h*5+3] + e4*swg[h*5+4] + sbg[h];
            eb[h][m] = bias / (1.0f + __expf(-gx));
        }
        any |= mk[m];
    }
    any = __syncthreads_or(any);

    const int rowvalid = (mk[n] != 0) && any;
    if (!rowvalid) {
        const float u = 1.0f / (float)N_;
#pragma unroll
        for (int h = 0; h < H_; h++) {
            float* srow = g_s + ((size_t)((b*H_ + h)*N_) + n) * N_;
#pragma unroll
            for (int kk = 0; kk < 4; kk++) srow[tid + kk*256] = u;
        }
        return;
    }

    const int wid = tid >> 5, lane = tid & 31;
#pragma unroll
    for (int h = 0; h < H_; h++) {
        float* srow = g_s + ((size_t)((b*H_ + h)*N_) + n) * N_;
        float v[4]; int vm[4];
        float mx = -3.402823466e38f;
#pragma unroll
        for (int kk = 0; kk < 4; kk++) {
            int m = tid + kk*256;
            vm[kk] = mk[m];
            float s = srow[m] + eb[h][m];
            v[kk] = s;
            if (vm[kk]) mx = fmaxf(mx, s);
        }
#pragma unroll
        for (int o = 16; o; o >>= 1) mx = fmaxf(mx, __shfl_xor_sync(0xffffffffu, mx, o));
        if (lane == 0) red_max[wid] = mx;
        __syncthreads();
        float mxa = red_max[0];
#pragma unroll
        for (int i = 1; i < 8; i++) mxa = fmaxf(mxa, red_max[i]);

        float sum = 0.f;
#pragma unroll
        for (int kk = 0; kk < 4; kk++) {
            float e = vm[kk] ? __expf(v[kk] - mxa) : 0.f;
            v[kk] = e; sum += e;
        }
#pragma unroll
        for (int o = 16; o; o >>= 1) sum += __shfl_xor_sync(0xffffffffu, sum, o);
        if (lane == 0) red_sum[wid] = sum;
        __syncthreads();
        float tot = 0.f;
#pragma unroll
        for (int i = 0; i < 8; i++) tot += red_sum[i];
        float inv = 1.0f / tot;
#pragma unroll
        for (int kk = 0; kk < 4; kk++) srow[tid + kk*256] = v[kk]*inv;
        __syncthreads();
    }
}

// ============================================================
// K4: g_att = attn @ v per (b,h). mma.sync bf16 hi/lo split.
// Block tile 128(n) x 64(d), K=1024 in 16 chunks of 64. V pre-transposed [d][m].
// 8 warps = 4(m) x 2(n); warp tile 32x32.
// ============================================================
#define AV_AH 0
#define AV_AL 16384
#define AV_BH 32768
#define AV_BL 40960
#define AV_SMEM 49152

__global__ void __launch_bounds__(256) av_mma() {
    extern __shared__ char sm[];
    const uint32_t sb = smem_u32(sm);
    const int tid = threadIdx.x, lane = tid & 31, wid = tid >> 5;
    const int z = blockIdx.y, n0 = blockIdx.x * 128;

    const float* A  = g_s + (size_t)z*N_*N_ + (size_t)n0*N_;   // attn rows n0..+127
    const float* Vt = g_v + (size_t)z*HD_*N_;                  // [d][m]

    const int warp_m = (wid & 3) * 32, warp_n = (wid >> 2) * 32;
    float c[2][4][4];
#pragma unroll
    for (int i = 0; i < 2; i++)
#pragma unroll
        for (int j = 0; j < 4; j++)
#pragma unroll
            for (int q = 0; q < 4; q++) c[i][j][q] = 0.f;

    const int row = tid >> 1, hc = (tid & 1) * 32;
    const int lr = (lane & 7) + ((lane >> 3) & 1) * 8;
    const int lk = (lane >> 4) * 16;

    for (int ch = 0; ch < 16; ch++) {
        const int mb = ch * 64;
        cvt32(A + (size_t)row*N_ + mb + hc, sm+AV_AH, sm+AV_AL, row*128 + hc*2);
        if (tid < 128) {
            const int d = tid >> 1, h2 = (tid & 1) * 32;
            cvt32(Vt + (size_t)d*N_ + mb + h2, sm+AV_BH, sm+AV_BL, d*128 + h2*2);
        }
        __syncthreads();

#pragma unroll
        for (int k0 = 0; k0 < 64; k0 += 16) {
            const int kb = k0*2 + lk;
            uint32_t ah[2][4], al[2][4], bh[4][2], bl[4][2];
#pragma unroll
            for (int mf = 0; mf < 2; mf++) {
                const int r = warp_m + mf*16 + lr;
                ldm_x4(sb + AV_AH + SWZ(r*128 + kb), ah[mf][0], ah[mf][1], ah[mf][2], ah[mf][3]);
                ldm_x4(sb + AV_AL + SWZ(r*128 + kb), al[mf][0], al[mf][1], al[mf][2], al[mf][3]);
            }
#pragma unroll
            for (int nb = 0; nb < 2; nb++) {
                const int r = warp_n + nb*16 + lr;
                uint32_t r0, r1, r2, r3;
                ldm_x4(sb + AV_BH + SWZ(r*128 + kb), r0, r1, r2, r3);
                bh[nb*2][0] = r0; bh[nb*2][1] = r2; bh[nb*2+1][0] = r1; bh[nb*2+1][1] = r3;
                ldm_x4(sb + AV_BL + SWZ(r*128 + kb), r0, r1, r2, r3);
                bl[nb*2][0] = r0; bl[nb*2][1] = r2; bl[nb*2+1][0] = r1; bl[nb*2+1][1] = r3;
            }
#pragma unroll
            for (int mf = 0; mf < 2; mf++)
#pragma unroll
                for (int nf = 0; nf < 4; nf++) {
                    mma_bf16(c[mf][nf], ah[mf], bh[nf]);
                    mma_bf16(c[mf][nf], ah[mf], bl[nf]);
                    mma_bf16(c[mf][nf], al[mf], bh[nf]);
                }
        }
        __syncthreads();
    }

    // epilogue
    const int b = z >> 3, h = z & 7;
    const int er = lane >> 2, ec = (lane & 3) * 2;
#pragma unroll
    for (int mf = 0; mf < 2; mf++)
#pragma unroll
        for (int nf = 0; nf < 4; nf++) {
            const int rr = n0 + warp_m + mf*16 + er;
            const int cc = h*HD_ + warp_n + nf*8 + ec;
            *(float2*)&g_att[(size_t)(b*N_ + rr)*D_ + cc] =
                make_float2(c[mf][nf][0], c[mf][nf][1]);
            *(float2*)&g_att[(size_t)(b*N_ + rr + 8)*D_ + cc] =
                make_float2(c[mf][nf][2], c[mf][nf][3]);
        }
}

// ============================================================
// K5: out = g_att @ w_proj^T + b_proj (unchanged)
// ============================================================
__global__ __launch_bounds__(256) void proj_gemm(const float* __restrict__ w,
                                                 const float* __restrict__ bias,
                                                 float* __restrict__ out) {
    __shared__ float As[8][128];
    __shared__ float Bs[8][128];
    const int tid = threadIdx.x;
    const int m0 = blockIdx.y * 128;
    const int c0 = blockIdx.x * 128;
    const int tx = tid & 15, ty = tid >> 4;
    float acc[8][8];
#pragma unroll
    for (int i = 0; i < 8; i++)
#pragma unroll
        for (int j = 0; j < 8; j++) acc[i][j] = 0.f;

    const int lrow = tid >> 1;
    const int lc   = (tid & 1) * 4;
    const float* ap = g_att + (size_t)(m0 + lrow) * D_ + lc;
    const float* bp = w     + (size_t)(c0 + lrow) * D_ + lc;

    for (int k0 = 0; k0 < D_; k0 += 8) {
        float4 av = *(const float4*)(ap + k0);
        float4 bv = *(const float4*)(bp + k0);
        As[lc+0][lrow] = av.x; As[lc+1][lrow] = av.y;
        As[lc+2][lrow] = av.z; As[lc+3][lrow] = av.w;
        Bs[lc+0][lrow] = bv.x; Bs[lc+1][lrow] = bv.y;
        Bs[lc+2][lrow] = bv.z; Bs[lc+3][lrow] = bv.w;
        __syncthreads();
#pragma unroll
        for (int k = 0; k < 8; k++) {
            float4 a0 = *(const float4*)&As[k][ty*8];
            float4 a1 = *(const float4*)&As[k][ty*8+4];
            float4 b0 = *(const float4*)&Bs[k][tx*8];
            float4 b1 = *(const float4*)&Bs[k][tx*8+4];
            float a[8] = {a0.x,a0.y,a0.z,a0.w,a1.x,a1.y,a1.z,a1.w};
            float b[8] = {b0.x,b0.y,b0.z,b0.w,b1.x,b1.y,b1.z,b1.w};
#pragma unroll
            for (int i = 0; i < 8; i++)
#pragma unroll
                for (int j = 0; j < 8; j++) acc[i][j] += a[i]*b[j];
        }
        __syncthreads();
    }
    float4 bi0 = *(const float4*)&bias[c0 + tx*8];
    float4 bi1 = *(const float4*)&bias[c0 + tx*8 + 4];
#pragma unroll
    for (int i = 0; i < 8; i++) {
        int m = m0 + ty*8 + i;
        float4 o0 = make_float4(acc[i][0]+bi0.x, acc[i][1]+bi0.y,
                                acc[i][2]+bi0.z, acc[i][3]+bi0.w);
        float4 o1 = make_float4(acc[i][4]+bi1.x, acc[i][5]+bi1.y,
                                acc[i][6]+bi1.z, acc[i][7]+bi1.w);
        float4* p = (float4*)(out + (size_t)m * D_ + c0 + tx*8);
        p[0] = o0; p[1] = o1;
    }
}

// ============================================================
extern "C" void kernel_launch(void* const* d_in, const int* in_sizes, int n_in,
                              void* d_out, int out_size) {
    const float* x      = (const float*)d_in[0];
    const float* edge   = (const float*)d_in[1];
    const int*   mask   = (const int*)d_in[2];
    const float* w_qkv  = (const float*)d_in[3];
    const float* w_ep   = (const float*)d_in[4];
    const float* w_eg   = (const float*)d_in[5];
    const float* b_eg   = (const float*)d_in[6];
    const float* w_proj = (const float*)d_in[7];
    const float* b_proj = (const float*)d_in[8];
    float* out = (float*)d_out;

    cudaFuncSetAttribute(qk_mma, cudaFuncAttributeMaxDynamicSharedMemorySize, QK_SMEM);
    cudaFuncSetAttribute(av_mma, cudaFuncAttributeMaxDynamicSharedMemorySize, AV_SMEM);

    qkv_gemm    <<<dim3(3*D_/128, B_*N_/128), 256>>>(x, w_qkv);
    qk_mma      <<<dim3(N_/128, N_/128, B_*H_), 256, QK_SMEM>>>();
    bias_softmax<<<B_*N_, 256>>>(edge, mask, w_ep, w_eg, b_eg);
    av_mma      <<<dim3(N_/128, B_*H_), 256, AV_SMEM>>>();
    proj_gemm   <<<dim3(D_/128, B_*N_/128), 256>>>(w_proj, b_proj, out);
}

// round 17
// speedup vs baseline: 1.5549x; 1.4143x over previous
#include <cuda_runtime.h>
#include <cuda_bf16.h>
#include <cstdint>

#define B_  4
#define N_  1024
#define D_  512
#define H_  8
#define E_  5
#define HD_ 64

// ---- scratch (static device globals) ----
// q,k: (b,h,n,hd) as packed bf16x2 (hi and lo parts)
__device__ uint32_t g_qh32[B_*H_*N_*(HD_/2)];
__device__ uint32_t g_ql32[B_*H_*N_*(HD_/2)];
__device__ uint32_t g_kh32[B_*H_*N_*(HD_/2)];
__device__ uint32_t g_kl32[B_*H_*N_*(HD_/2)];
// v: (b,h,hd,n) bf16 hi/lo (transposed)
__device__ __nv_bfloat16 g_vh[B_*H_*HD_*N_];
__device__ __nv_bfloat16 g_vl[B_*H_*HD_*N_];
// scores fp32, attn probabilities bf16 hi/lo
__device__ float g_s[(size_t)B_*H_*N_*N_];
__device__ __nv_bfloat16 g_ph[(size_t)B_*H_*N_*N_];
__device__ __nv_bfloat16 g_pl[(size_t)B_*H_*N_*N_];
__device__ float g_att[B_*N_*D_];

// ============================================================
// helpers
// ============================================================
__device__ __forceinline__ uint32_t smem_u32(const void* p) {
    uint32_t a;
    asm("{ .reg .u64 t; cvta.to.shared.u64 t, %1; cvt.u32.u64 %0, t; }"
        : "=r"(a) : "l"(p));
    return a;
}
#define SWZ(off) ((off) ^ (((off) >> 3) & 0x70))

__device__ __forceinline__ void ldm_x4(uint32_t addr, uint32_t& r0, uint32_t& r1,
                                       uint32_t& r2, uint32_t& r3) {
    asm volatile("ldmatrix.sync.aligned.m8n8.x4.shared.b16 {%0,%1,%2,%3}, [%4];"
                 : "=r"(r0), "=r"(r1), "=r"(r2), "=r"(r3) : "r"(addr));
}
__device__ __forceinline__ void mma_bf16(float* c, const uint32_t* a, const uint32_t* b) {
    asm volatile("mma.sync.aligned.m16n8k16.row.col.f32.bf16.bf16.f32 "
                 "{%0,%1,%2,%3}, {%4,%5,%6,%7}, {%8,%9}, {%0,%1,%2,%3};"
                 : "+f"(c[0]), "+f"(c[1]), "+f"(c[2]), "+f"(c[3])
                 : "r"(a[0]), "r"(a[1]), "r"(a[2]), "r"(a[3]), "r"(b[0]), "r"(b[1]));
}
__device__ __forceinline__ void cp16(uint32_t dst, const void* src) {
    asm volatile("cp.async.cg.shared.global [%0], [%1], 16;"
                 :: "r"(dst), "l"(src) : "memory");
}
#define CP_COMMIT() asm volatile("cp.async.commit_group;" ::: "memory")
#define CP_WAIT(n)  asm volatile("cp.async.wait_group %0;" :: "n"(n) : "memory")

__device__ __forceinline__ uint32_t packbf(__nv_bfloat16 a, __nv_bfloat16 b) {
    __nv_bfloat162 t = __halves2bfloat162(a, b);
    return *reinterpret_cast<uint32_t*>(&t);
}
__device__ __forceinline__ void split2(float v0, float v1, uint32_t& hi, uint32_t& lo) {
    __nv_bfloat16 h0 = __float2bfloat16(v0), h1 = __float2bfloat16(v1);
    hi = packbf(h0, h1);
    lo = packbf(__float2bfloat16(v0 - __bfloat162float(h0)),
                __float2bfloat16(v1 - __bfloat162float(h1)));
}

// convert 32 fp32 -> hi/lo bf16, store swizzled into 128B-row smem tiles
__device__ __forceinline__ void cvt32(const float* __restrict__ src,
                                      char* hi, char* lo, int byte_base) {
#pragma unroll
    for (int p = 0; p < 8; p++) {
        float4 x = *(const float4*)(src + p*4);
        __nv_bfloat162 h01 = __floats2bfloat162_rn(x.x, x.y);
        __nv_bfloat162 h23 = __floats2bfloat162_rn(x.z, x.w);
        float l0 = x.x - __bfloat162float(h01.x);
        float l1 = x.y - __bfloat162float(h01.y);
        float l2 = x.z - __bfloat162float(h23.x);
        float l3 = x.w - __bfloat162float(h23.y);
        __nv_bfloat162 g01 = __floats2bfloat162_rn(l0, l1);
        __nv_bfloat162 g23 = __floats2bfloat162_rn(l2, l3);
        int o0 = SWZ(byte_base + p*8);
        int o1 = SWZ(byte_base + p*8 + 4);
        *(uint32_t*)(hi + o0) = *(uint32_t*)&h01;
        *(uint32_t*)(hi + o1) = *(uint32_t*)&h23;
        *(uint32_t*)(lo + o0) = *(uint32_t*)&g01;
        *(uint32_t*)(lo + o1) = *(uint32_t*)&g23;
    }
}

// ============================================================
// K1: qkv = x @ w_qkv^T via mma.sync bf16 hi/lo (3 passes).
// Block 128(m) x 128(c), K=512 in 8 chunks of 64.
// Epilogue: q,k -> hi/lo bf16 (b,h,n,hd); v -> hi/lo bf16 transposed (b,h,hd,n)
// ============================================================
#define QKV_AH 0
#define QKV_AL 16384
#define QKV_BH 32768
#define QKV_BL 49152
#define QKV_SMEM 65536

__global__ void __launch_bounds__(256) qkv_mma(const float* __restrict__ x,
                                               const float* __restrict__ w) {
    extern __shared__ char sm[];
    const uint32_t sb = smem_u32(sm);
    const int tid = threadIdx.x, lane = tid & 31, wid = tid >> 5;
    const int m0 = blockIdx.y * 128, c0 = blockIdx.x * 128;

    const int warp_m = (wid & 3) * 32, warp_c = (wid >> 2) * 64;
    float c[2][8][4];
#pragma unroll
    for (int i = 0; i < 2; i++)
#pragma unroll
        for (int j = 0; j < 8; j++)
#pragma unroll
            for (int q = 0; q < 4; q++) c[i][j][q] = 0.f;

    const int row = tid >> 1, hc = (tid & 1) * 32;
    const int lr = (lane & 7) + ((lane >> 3) & 1) * 8;
    const int lk = (lane >> 4) * 16;

    for (int ch = 0; ch < 8; ch++) {
        cvt32(x + (size_t)(m0 + row)*D_ + ch*64 + hc, sm+QKV_AH, sm+QKV_AL, row*128 + hc*2);
        cvt32(w + (size_t)(c0 + row)*D_ + ch*64 + hc, sm+QKV_BH, sm+QKV_BL, row*128 + hc*2);
        __syncthreads();
#pragma unroll
        for (int k0 = 0; k0 < 64; k0 += 16) {
            const int kb = k0*2 + lk;
            uint32_t ah[2][4], al[2][4], bh[8][2], bl[8][2];
#pragma unroll
            for (int mf = 0; mf < 2; mf++) {
                const int r = warp_m + mf*16 + lr;
                ldm_x4(sb + QKV_AH + SWZ(r*128 + kb), ah[mf][0], ah[mf][1], ah[mf][2], ah[mf][3]);
                ldm_x4(sb + QKV_AL + SWZ(r*128 + kb), al[mf][0], al[mf][1], al[mf][2], al[mf][3]);
            }
#pragma unroll
            for (int nb = 0; nb < 4; nb++) {
                const int r = warp_c + nb*16 + lr;
                uint32_t r0, r1, r2, r3;
                ldm_x4(sb + QKV_BH + SWZ(r*128 + kb), r0, r1, r2, r3);
                bh[nb*2][0] = r0; bh[nb*2][1] = r2; bh[nb*2+1][0] = r1; bh[nb*2+1][1] = r3;
                ldm_x4(sb + QKV_BL + SWZ(r*128 + kb), r0, r1, r2, r3);
                bl[nb*2][0] = r0; bl[nb*2][1] = r2; bl[nb*2+1][0] = r1; bl[nb*2+1][1] = r3;
            }
#pragma unroll
            for (int mf = 0; mf < 2; mf++)
#pragma unroll
                for (int nf = 0; nf < 8; nf++) {
                    mma_bf16(c[mf][nf], ah[mf], bh[nf]);
                    mma_bf16(c[mf][nf], ah[mf], bl[nf]);
                    mma_bf16(c[mf][nf], al[mf], bh[nf]);
                }
        }
        __syncthreads();
    }

    // epilogue: split and scatter
    const int er = lane >> 2, ec = (lane & 3) * 2;
#pragma unroll
    for (int mf = 0; mf < 2; mf++)
#pragma unroll
        for (int nf = 0; nf < 8; nf++) {
            const int cgl = c0 + warp_c + nf*8 + ec;
            const int part = cgl >> 9, h = (cgl >> 6) & 7, hd = cgl & 63;
#pragma unroll
            for (int rh = 0; rh < 2; rh++) {
                const int m = m0 + warp_m + mf*16 + er + rh*8;
                const int bb = m >> 10, n = m & 1023;
                uint32_t hi, lo;
                split2(c[mf][nf][rh*2+0], c[mf][nf][rh*2+1], hi, lo);
                if (part == 0) {
                    const int off = ((bb*H_ + h)*N_ + n)*(HD_/2) + (hd >> 1);
                    g_qh32[off] = hi; g_ql32[off] = lo;
                } else if (part == 1) {
                    const int off = ((bb*H_ + h)*N_ + n)*(HD_/2) + (hd >> 1);
                    g_kh32[off] = hi; g_kl32[off] = lo;
                } else {
                    const size_t o0 = ((size_t)(bb*H_ + h)*HD_ + hd)*N_ + n;
                    __nv_bfloat162 h2 = *reinterpret_cast<__nv_bfloat162*>(&hi);
                    __nv_bfloat162 l2 = *reinterpret_cast<__nv_bfloat162*>(&lo);
                    g_vh[o0] = h2.x; g_vl[o0] = l2.x;
                    g_vh[o0 + N_] = h2.y; g_vl[o0 + N_] = l2.y;
                }
            }
        }
}

// ============================================================
// K2: g_s = 0.125 * q @ k^T per (b,h). cp.async staging of pre-split q/k.
// ============================================================
#define QK_AH 0
#define QK_AL 16384
#define QK_BH 32768
#define QK_BL 49152
#define QK_SMEM 65536

__global__ void __launch_bounds__(256) qk_mma() {
    extern __shared__ char sm[];
    const uint32_t sb = smem_u32(sm);
    const int tid = threadIdx.x, lane = tid & 31, wid = tid >> 5;
    const int z = blockIdx.z, n0 = blockIdx.y * 128, m0 = blockIdx.x * 128;

    // stage all 4 tiles: rows of 64 bf16 = 128B
#pragma unroll
    for (int t = 0; t < 4; t++) {
        const int idx = tid + t*256;          // 0..1023
        const int r = idx >> 3, cb = (idx & 7) * 16;
        const uint32_t sw = SWZ(r*128 + cb);
        const size_t qoff = ((size_t)z*N_ + n0 + r) * 128 + cb;   // bytes
        const size_t koff = ((size_t)z*N_ + m0 + r) * 128 + cb;
        cp16(sb + QK_AH + sw, (const char*)g_qh32 + qoff);
        cp16(sb + QK_AL + sw, (const char*)g_ql32 + qoff);
        cp16(sb + QK_BH + sw, (const char*)g_kh32 + koff);
        cp16(sb + QK_BL + sw, (const char*)g_kl32 + koff);
    }
    CP_COMMIT();
    CP_WAIT(0);
    __syncthreads();

    const int warp_m = (wid & 3) * 32, warp_n = (wid >> 2) * 64;
    float c[2][8][4];
#pragma unroll
    for (int i = 0; i < 2; i++)
#pragma unroll
        for (int j = 0; j < 8; j++)
#pragma unroll
            for (int q = 0; q < 4; q++) c[i][j][q] = 0.f;

    const int lr = (lane & 7) + ((lane >> 3) & 1) * 8;
    const int lk = (lane >> 4) * 16;

#pragma unroll
    for (int k0 = 0; k0 < 64; k0 += 16) {
        const int kb = k0*2 + lk;
        uint32_t ah[2][4], al[2][4], bh[8][2], bl[8][2];
#pragma unroll
        for (int mf = 0; mf < 2; mf++) {
            const int r = warp_m + mf*16 + lr;
            ldm_x4(sb + QK_AH + SWZ(r*128 + kb), ah[mf][0], ah[mf][1], ah[mf][2], ah[mf][3]);
            ldm_x4(sb + QK_AL + SWZ(r*128 + kb), al[mf][0], al[mf][1], al[mf][2], al[mf][3]);
        }
#pragma unroll
        for (int nb = 0; nb < 4; nb++) {
            const int r = warp_n + nb*16 + lr;
            uint32_t r0, r1, r2, r3;
            ldm_x4(sb + QK_BH + SWZ(r*128 + kb), r0, r1, r2, r3);
            bh[nb*2][0] = r0; bh[nb*2][1] = r2; bh[nb*2+1][0] = r1; bh[nb*2+1][1] = r3;
            ldm_x4(sb + QK_BL + SWZ(r*128 + kb), r0, r1, r2, r3);
            bl[nb*2][0] = r0; bl[nb*2][1] = r2; bl[nb*2+1][0] = r1; bl[nb*2+1][1] = r3;
        }
#pragma unroll
        for (int mf = 0; mf < 2; mf++)
#pragma unroll
            for (int nf = 0; nf < 8; nf++) {
                mma_bf16(c[mf][nf], ah[mf], bh[nf]);
                mma_bf16(c[mf][nf], ah[mf], bl[nf]);
                mma_bf16(c[mf][nf], al[mf], bh[nf]);
            }
    }

    const float sc = 0.125f;
    const int er = lane >> 2, ec = (lane & 3) * 2;
    float* C = g_s + (size_t)z*N_*N_;
#pragma unroll
    for (int mf = 0; mf < 2; mf++)
#pragma unroll
        for (int nf = 0; nf < 8; nf++) {
            const int rr = n0 + warp_m + mf*16 + er;
            const int cc = m0 + warp_n + nf*8 + ec;
            *(float2*)&C[(size_t)rr*N_ + cc] =
                make_float2(sc*c[mf][nf][0], sc*c[mf][nf][1]);
            *(float2*)&C[(size_t)(rr+8)*N_ + cc] =
                make_float2(sc*c[mf][nf][2], sc*c[mf][nf][3]);
        }
}

// ============================================================
// K3: fused edge-bias + masked softmax. sigmoid via tanh.approx (1 MUFU).
// Writes attn as hi/lo bf16 (packed u32 stores).
// ============================================================
__global__ __launch_bounds__(256) void bias_softmax(const float* __restrict__ edge,
                                                    const int* __restrict__ mask,
                                                    const float* __restrict__ w_ep,
                                                    const float* __restrict__ w_eg,
                                                    const float* __restrict__ b_eg) {
    __shared__ float eb[H_][N_];
    __shared__ unsigned char mk[N_];
    __shared__ float swp[H_*E_], swg[H_*E_], sbg[H_];
    __shared__ float red_max[8], red_sum[8];

    const int tid = threadIdx.x;
    const int bn  = blockIdx.x;
    const int b   = bn >> 10, n = bn & 1023;

    if (tid < H_*E_)                 swp[tid]           = w_ep[tid];
    else if (tid < 2*H_*E_)          swg[tid - H_*E_]   = w_eg[tid - H_*E_];
    else if (tid < 2*H_*E_ + H_)     sbg[tid - 2*H_*E_] = b_eg[tid - 2*H_*E_];

    for (int m = tid; m < N_; m += 256)
        mk[m] = (mask[b*N_ + m] != 0) ? 1 : 0;
    __syncthreads();

    const float* erow = edge + (size_t)bn * (N_*E_);
    int any = 0;
    for (int m = tid; m < N_; m += 256) {
        const float* e = erow + m*E_;
        float e0 = e[0], e1 = e[1], e2 = e[2], e3 = e[3], e4 = e[4];
#pragma unroll
        for (int h = 0; h < H_; h++) {
            float bias = e0*swp[h*5+0] + e1*swp[h*5+1] + e2*swp[h*5+2]
                       + e3*swp[h*5+3] + e4*swp[h*5+4];
            float gx   = e0*swg[h*5+0] + e1*swg[h*5+1] + e2*swg[h*5+2]
                       + e3*swg[h*5+3] + e4*swg[h*5+4] + sbg[h];
            float th;
            asm("tanh.approx.f32 %0, %1;" : "=f"(th) : "f"(0.5f*gx));
            eb[h][m] = bias * (0.5f*th + 0.5f);   // sigmoid(gx)*bias
        }
        any |= mk[m];
    }
    any = __syncthreads_or(any);

    const int rowvalid = (mk[n] != 0) && any;
    if (!rowvalid) {
        // uniform 1/1024 = 2^-10 (exact in bf16), lo = 0
#pragma unroll
        for (int h = 0; h < H_; h++) {
            const size_t r = (size_t)((b*H_ + h)*N_) + n;
            uint32_t* ph32 = (uint32_t*)((char*)g_ph + r*(N_*2));
            uint32_t* pl32 = (uint32_t*)((char*)g_pl + r*(N_*2));
            ph32[tid*2 + 0] = 0x3A803A80u; ph32[tid*2 + 1] = 0x3A803A80u;
            pl32[tid*2 + 0] = 0u;          pl32[tid*2 + 1] = 0u;
        }
        return;
    }

    const int wid = tid >> 5, lane = tid & 31;
    int vm[4];
#pragma unroll
    for (int kk = 0; kk < 4; kk++) vm[kk] = mk[tid*4 + kk];

#pragma unroll
    for (int h = 0; h < H_; h++) {
        const size_t r = (size_t)((b*H_ + h)*N_) + n;
        const float* srow = g_s + r * N_;
        float4 sv = *(const float4*)&srow[tid*4];
        float v[4] = {sv.x + eb[h][tid*4+0], sv.y + eb[h][tid*4+1],
                      sv.z + eb[h][tid*4+2], sv.w + eb[h][tid*4+3]};
        float mx = -3.402823466e38f;
#pragma unroll
        for (int kk = 0; kk < 4; kk++)
            if (vm[kk]) mx = fmaxf(mx, v[kk]);
#pragma unroll
        for (int o = 16; o; o >>= 1) mx = fmaxf(mx, __shfl_xor_sync(0xffffffffu, mx, o));
        if (lane == 0) red_max[wid] = mx;
        __syncthreads();
        float mxa = red_max[0];
#pragma unroll
        for (int i = 1; i < 8; i++) mxa = fmaxf(mxa, red_max[i]);

        float sum = 0.f;
#pragma unroll
        for (int kk = 0; kk < 4; kk++) {
            float e = vm[kk] ? __expf(v[kk] - mxa) : 0.f;
            v[kk] = e; sum += e;
        }
#pragma unroll
        for (int o = 16; o; o >>= 1) sum += __shfl_xor_sync(0xffffffffu, sum, o);
        if (lane == 0) red_sum[wid] = sum;
        __syncthreads();
        float tot = 0.f;
#pragma unroll
        for (int i = 0; i < 8; i++) tot += red_sum[i];
        float inv = 1.0f / tot;

        uint32_t h01, l01, h23, l23;
        split2(v[0]*inv, v[1]*inv, h01, l01);
        split2(v[2]*inv, v[3]*inv, h23, l23);
        uint32_t* ph32 = (uint32_t*)((char*)g_ph + r*(N_*2));
        uint32_t* pl32 = (uint32_t*)((char*)g_pl + r*(N_*2));
        ph32[tid*2 + 0] = h01; ph32[tid*2 + 1] = h23;
        pl32[tid*2 + 0] = l01; pl32[tid*2 + 1] = l23;
        __syncthreads();
    }
}

// ============================================================
// K4: g_att = attn @ v per (b,h). cp.async double-buffered, pre-split inputs.
// Block tile 128(n) x 64(d), K=1024 in 16 chunks of 64.
// ============================================================
#define AV_BUF 49152   // per-buffer: Ah 16K | Al 16K | Bh 8K | Bl 8K
#define AV_SMEM (2*AV_BUF)

__global__ void __launch_bounds__(256) av_mma() {
    extern __shared__ char sm[];
    const uint32_t sb = smem_u32(sm);
    const int tid = threadIdx.x, lane = tid & 31, wid = tid >> 5;
    const int z = blockIdx.y, n0 = blockIdx.x * 128;

    const size_t abase = ((size_t)z*N_ + n0) * N_;   // elt offset in g_ph/g_pl
    const size_t vbase = (size_t)z * HD_ * N_;       // elt offset in g_vh/g_vl

    auto stage = [&](int ch) {
        const int mb = ch * 64;
        const uint32_t d = sb + (ch & 1) * AV_BUF;
#pragma unroll
        for (int t = 0; t < 4; t++) {
            const int idx = tid + t*256;              // 0..1023
            const int r = idx >> 3, cb = (idx & 7) * 16;
            const uint32_t sw = SWZ(r*128 + cb);
            const size_t off = (abase + (size_t)r*N_ + mb)*2 + cb;
            cp16(d + 0     + sw, (const char*)g_ph + off);
            cp16(d + 16384 + sw, (const char*)g_pl + off);
        }
#pragma unroll
        for (int t = 0; t < 2; t++) {
            const int idx = tid + t*256;              // 0..511
            const int r = idx >> 3, cb = (idx & 7) * 16;
            const uint32_t sw = SWZ(r*128 + cb);
            const size_t off = (vbase + (size_t)r*N_ + mb)*2 + cb;
            cp16(d + 32768 + sw, (const char*)g_vh + off);
            cp16(d + 40960 + sw, (const char*)g_vl + off);
        }
    };

    const int warp_m = (wid & 3) * 32, warp_n = (wid >> 2) * 32;
    float c[2][4][4];
#pragma unroll
    for (int i = 0; i < 2; i++)
#pragma unroll
        for (int j = 0; j < 4; j++)
#pragma unroll
            for (int q = 0; q < 4; q++) c[i][j][q] = 0.f;

    const int lr = (lane & 7) + ((lane >> 3) & 1) * 8;
    const int lk = (lane >> 4) * 16;

    stage(0);
    CP_COMMIT();

    for (int ch = 0; ch < 16; ch++) {
        if (ch < 15) {
            stage(ch + 1);
            CP_COMMIT();
            CP_WAIT(1);
        } else {
            CP_WAIT(0);
        }
        __syncthreads();

        const uint32_t base = sb + (ch & 1) * AV_BUF;
#pragma unroll
        for (int k0 = 0; k0 < 64; k0 += 16) {
            const int kb = k0*2 + lk;
            uint32_t ah[2][4], al[2][4], bh[4][2], bl[4][2];
#pragma unroll
            for (int mf = 0; mf < 2; mf++) {
                const int r = warp_m + mf*16 + lr;
                ldm_x4(base + 0     + SWZ(r*128 + kb), ah[mf][0], ah[mf][1], ah[mf][2], ah[mf][3]);
                ldm_x4(base + 16384 + SWZ(r*128 + kb), al[mf][0], al[mf][1], al[mf][2], al[mf][3]);
            }
#pragma unroll
            for (int nb = 0; nb < 2; nb++) {
                const int r = warp_n + nb*16 + lr;
                uint32_t r0, r1, r2, r3;
                ldm_x4(base + 32768 + SWZ(r*128 + kb), r0, r1, r2, r3);
                bh[nb*2][0] = r0; bh[nb*2][1] = r2; bh[nb*2+1][0] = r1; bh[nb*2+1][1] = r3;
                ldm_x4(base + 40960 + SWZ(r*128 + kb), r0, r1, r2, r3);
                bl[nb*2][0] = r0; bl[nb*2][1] = r2; bl[nb*2+1][0] = r1; bl[nb*2+1][1] = r3;
            }
#pragma unroll
            for (int mf = 0; mf < 2; mf++)
#pragma unroll
                for (int nf = 0; nf < 4; nf++) {
                    mma_bf16(c[mf][nf], ah[mf], bh[nf]);
                    mma_bf16(c[mf][nf], al[mf], bh[nf]);
                    mma_bf16(c[mf][nf], ah[mf], bl[nf]);
                }
        }
        __syncthreads();
    }

    const int b = z >> 3, h = z & 7;
    const int er = lane >> 2, ec = (lane & 3) * 2;
#pragma unroll
    for (int mf = 0; mf < 2; mf++)
#pragma unroll
        for (int nf = 0; nf < 4; nf++) {
            const int rr = n0 + warp_m + mf*16 + er;
            const int cc = h*HD_ + warp_n + nf*8 + ec;
            *(float2*)&g_att[(size_t)(b*N_ + rr)*D_ + cc] =
                make_float2(c[mf][nf][0], c[mf][nf][1]);
            *(float2*)&g_att[(size_t)(b*N_ + rr + 8)*D_ + cc] =
                make_float2(c[mf][nf][2], c[mf][nf][3]);
        }
}

// ============================================================
// K5: out = g_att @ w_proj^T + b_proj (SIMT fp32, unchanged)
// ============================================================
__global__ __launch_bounds__(256) void proj_gemm(const float* __restrict__ w,
                                                 const float* __restrict__ bias,
                                                 float* __restrict__ out) {
    __shared__ float As[8][128];
    __shared__ float Bs[8][128];
    const int tid = threadIdx.x;
    const int m0 = blockIdx.y * 128;
    const int c0 = blockIdx.x * 128;
    const int tx = tid & 15, ty = tid >> 4;
    float acc[8][8];
#pragma unroll
    for (int i = 0; i < 8; i++)
#pragma unroll
        for (int j = 0; j < 8; j++) acc[i][j] = 0.f;

    const int lrow = tid >> 1;
    const int lc   = (tid & 1) * 4;
    const float* ap = g_att + (size_t)(m0 + lrow) * D_ + lc;
    const float* bp = w     + (size_t)(c0 + lrow) * D_ + lc;

    for (int k0 = 0; k0 < D_; k0 += 8) {
        float4 av = *(const float4*)(ap + k0);
        float4 bv = *(const float4*)(bp + k0);
        As[lc+0][lrow] = av.x; As[lc+1][lrow] = av.y;
        As[lc+2][lrow] = av.z; As[lc+3][lrow] = av.w;
        Bs[lc+0][lrow] = bv.x; Bs[lc+1][lrow] = bv.y;
        Bs[lc+2][lrow] = bv.z; Bs[lc+3][lrow] = bv.w;
        __syncthreads();
#pragma unroll
        for (int k = 0; k < 8; k++) {
            float4 a0 = *(const float4*)&As[k][ty*8];
            float4 a1 = *(const float4*)&As[k][ty*8+4];
            float4 b0 = *(const float4*)&Bs[k][tx*8];
            float4 b1 = *(const float4*)&Bs[k][tx*8+4];
            float a[8] = {a0.x,a0.y,a0.z,a0.w,a1.x,a1.y,a1.z,a1.w};
            float b[8] = {b0.x,b0.y,b0.z,b0.w,b1.x,b1.y,b1.z,b1.w};
#pragma unroll
            for (int i = 0; i < 8; i++)
#pragma unroll
                for (int j = 0; j < 8; j++) acc[i][j] += a[i]*b[j];
        }
        __syncthreads();
    }
    float4 bi0 = *(const float4*)&bias[c0 + tx*8];
    float4 bi1 = *(const float4*)&bias[c0 + tx*8 + 4];
#pragma unroll
    for (int i = 0; i < 8; i++) {
        int m = m0 + ty*8 + i;
        float4 o0 = make_float4(acc[i][0]+bi0.x, acc[i][1]+bi0.y,
                                acc[i][2]+bi0.z, acc[i][3]+bi0.w);
        float4 o1 = make_float4(acc[i][4]+bi1.x, acc[i][5]+bi1.y,
                                acc[i][6]+bi1.z, acc[i][7]+bi1.w);
        float4* p = (float4*)(out + (size_t)m * D_ + c0 + tx*8);
        p[0] = o0; p[1] = o1;
    }
}

// ============================================================
extern "C" void kernel_launch(void* const* d_in, const int* in_sizes, int n_in,
                              void* d_out, int out_size) {
    const float* x      = (const float*)d_in[0];
    const float* edge   = (const float*)d_in[1];
    const int*   mask   = (const int*)d_in[2];
    const float* w_qkv  = (const float*)d_in[3];
    const float* w_ep   = (const float*)d_in[4];
    const float* w_eg   = (const float*)d_in[5];
    const float* b_eg   = (const float*)d_in[6];
    const float* w_proj = (const float*)d_in[7];
    const float* b_proj = (const float*)d_in[8];
    float* out = (float*)d_out;

    cudaFuncSetAttribute(qkv_mma, cudaFuncAttributeMaxDynamicSharedMemorySize, QKV_SMEM);
    cudaFuncSetAttribute(qk_mma,  cudaFuncAttributeMaxDynamicSharedMemorySize, QK_SMEM);
    cudaFuncSetAttribute(av_mma,  cudaFuncAttributeMaxDynamicSharedMemorySize, AV_SMEM);

    qkv_mma     <<<dim3(3*D_/128, B_*N_/128), 256, QKV_SMEM>>>(x, w_qkv);
    qk_mma      <<<dim3(N_/128, N_/128, B_*H_), 256, QK_SMEM>>>();
    bias_softmax<<<B_*N_, 256>>>(edge, mask, w_ep, w_eg, b_eg);
    av_mma      <<<dim3(N_/128, B_*H_), 256, AV_SMEM>>>();
    proj_gemm   <<<dim3(D_/128, B_*N_/128), 256>>>(w_proj, b_proj, out);
}